// round 15
// baseline (speedup 1.0000x reference)
#include <cuda_runtime.h>
#include <cstdint>

// Problem: states [B=64, L=4096, D=256] f32; w [256] f32; bias scalar f32.
// out[b,l] = reverse_cumsum_l( dot(states[b,l,:], w) + bias )
//
// ONE kernel, decoupled-lookback structure (CUB-style):
//   bids [0, 32768): dot blocks — exact R5 one-shot shape (87% of HBM):
//     256 thr, warp-per-row, __ldcs. Lane 0 stores the row value as a
//     64-bit (flag|float) packet to g_vals. No sync/fence added.
//   bids [32768, 33792): scan blocks — one per (batch, chunk of 256 l):
//     poll the 256 packets of their chunk (data travels IN the flag word
//     => no memory fences), consume-and-zero them (restores the replay
//     invariant), suffix-scan, publish chunk total packet in g_slots
//     (own slot zeroed at start; polled >=10us later), add later-chunk
//     totals, write out. All 1024 scan blocks co-resident => deadlock-free.

static constexpr int B = 64;
static constexpr int L = 4096;
static constexpr int D = 256;                  // 64 float4 per row
static constexpr int ROWS = B * L;             // 262144
static constexpr int DOT_BLOCKS = ROWS / 8;    // 32768
static constexpr int NB = 16;                  // chunks per batch
static constexpr int CHUNK = L / NB;           // 256
static constexpr int SCAN_BLOCKS = B * NB;     // 1024
static constexpr int GRID = DOT_BLOCKS + SCAN_BLOCKS;

__device__ unsigned long long g_vals[ROWS];        // value packets (2MB)
__device__ unsigned long long g_slots[SCAN_BLOCKS];// chunk-total packets

__device__ __forceinline__ void st_relaxed(unsigned long long* p,
                                           unsigned long long v) {
    asm volatile("st.global.relaxed.gpu.u64 [%0], %1;" :: "l"(p), "l"(v) : "memory");
}
__device__ __forceinline__ unsigned long long ld_relaxed(
        const unsigned long long* p) {
    unsigned long long v;
    asm volatile("ld.global.relaxed.gpu.u64 %0, [%1];" : "=l"(v) : "l"(p) : "memory");
    return v;
}

__global__ void __launch_bounds__(256)
qvalue_lookback(const float4* __restrict__ states4,
                const float4* __restrict__ w4,
                const float*  __restrict__ bias,
                float* __restrict__ out)
{
    const int t    = threadIdx.x;
    const int lane = t & 31;
    const int wid  = t >> 5;

    if (blockIdx.x < DOT_BLOCKS) {
        // ---------------- dot block: exact R5 one-shot shape ----------------
        int gwarp = (blockIdx.x << 3) + wid;

        const float4* row = states4 + (size_t)gwarp * (D / 4);

        float4 a0 = __ldcs(&row[lane]);
        float4 a1 = __ldcs(&row[lane + 32]);
        float4 w0 = __ldg(&w4[lane]);
        float4 w1 = __ldg(&w4[lane + 32]);

        float s = a0.x * w0.x + a0.y * w0.y + a0.z * w0.z + a0.w * w0.w
                + a1.x * w1.x + a1.y * w1.y + a1.z * w1.z + a1.w * w1.w;

        #pragma unroll
        for (int off = 16; off > 0; off >>= 1)
            s += __shfl_xor_sync(0xFFFFFFFFu, s, off);

        if (lane == 0) {
            float val = s + __ldg(bias);
            unsigned long long pkt =
                (1ULL << 32) | (unsigned long long)__float_as_uint(val);
            st_relaxed(&g_vals[gwarp], pkt);
        }
        return;
    }

    // ---------------- scan block ----------------
    __shared__ float warp_tot[8];
    __shared__ float warp_off[8];
    __shared__ float chunk_off_sh;

    const int sidx  = blockIdx.x - DOT_BLOCKS;   // 0..1023
    const int b     = sidx >> 4;
    const int j     = sidx & 15;
    const int chunk = 15 - j;                    // j=0 owns the LAST chunk

    // zero own total-slot first (polled by others >= microseconds later)
    if (t == 0)
        st_relaxed(&g_slots[sidx], 0ULL);

    // poll this chunk's 256 value packets (one per thread)
    const int idx = b * L + chunk * CHUNK + t;
    unsigned long long x = ld_relaxed(&g_vals[idx]);
    while (!(x >> 32)) {
        __nanosleep(100);
        x = ld_relaxed(&g_vals[idx]);
    }
    float v = __uint_as_float((unsigned)(x & 0xFFFFFFFFULL));
    st_relaxed(&g_vals[idx], 0ULL);              // consume: restore zeros

    // inclusive SUFFIX scan within warp: lane i -> sum over lanes >= i
    float s = v;
    #pragma unroll
    for (int off = 1; off < 32; off <<= 1) {
        float n = __shfl_down_sync(0xFFFFFFFFu, s, off);
        if (lane < 32 - off) s += n;
    }

    if (lane == 0) warp_tot[wid] = s;            // warp full sum
    __syncthreads();

    // publish this chunk's total ASAP
    if (t == 0) {
        float tot = 0.f;
        #pragma unroll
        for (int w = 0; w < 8; w++) tot += warp_tot[w];
        unsigned long long pkt =
            (1ULL << 32) | (unsigned long long)__float_as_uint(tot);
        st_relaxed(&g_slots[sidx], pkt);
    }

    // warp 0: suffix of warp totals (strictly after each warp)
    if (wid == 0) {
        float ws = (lane < 8) ? warp_tot[lane] : 0.f;
        float ss = ws;
        #pragma unroll
        for (int off = 1; off < 8; off <<= 1) {
            float n = __shfl_down_sync(0xFFFFFFFFu, ss, off);
            if (lane < 8 - off) ss += n;
        }
        if (lane < 8) warp_off[lane] = ss - ws;
    }

    // warp 1: poll totals of LATER chunks (= lower sidx, started earlier)
    if (wid == 1) {
        float p = 0.f;
        if (lane < j) {
            const unsigned long long* sp = &g_slots[(b << 4) | lane];
            unsigned long long y = ld_relaxed(sp);
            while (!(y >> 32)) {
                __nanosleep(60);
                y = ld_relaxed(sp);
            }
            p = __uint_as_float((unsigned)(y & 0xFFFFFFFFULL));
        }
        __syncwarp();
        #pragma unroll
        for (int off = 16; off > 0; off >>= 1)
            p += __shfl_xor_sync(0xFFFFFFFFu, p, off);
        if (lane == 0) chunk_off_sh = p;
    }
    __syncthreads();

    // q = (sum of later chunks) + (warps after mine) + (suffix incl. me)
    out[idx] = chunk_off_sh + warp_off[wid] + s;
}

extern "C" void kernel_launch(void* const* d_in, const int* in_sizes, int n_in,
                              void* d_out, int out_size)
{
    const float4* states4 = (const float4*)d_in[0];
    const float4* w4      = (const float4*)d_in[1];
    const float*  bias    = (const float*)d_in[2];
    float* out = (float*)d_out;

    qvalue_lookback<<<GRID, 256>>>(states4, w4, bias, out);
}

// round 16
// speedup vs baseline: 1.0950x; 1.0950x over previous
#include <cuda_runtime.h>
#include <cstdint>

// Problem: states [B=64, L=4096, D=256] f32; w [256] f32; bias scalar f32.
// out[b,l] = reverse_cumsum_l( dot(states[b,l,:], w) + bias )
//
// Two kernels (the only structure that reaches 87%+ of HBM):
//  1) dot_kernel: one-shot, 2 rows per warp => 4 front-batched LDG.128
//     per lane (2x the in-flight bytes of R5, which sat exactly at the
//     latency-coverage threshold). Value stores carry L2::evict_last so
//     the 1MB of values survives the 256MB evict_first stream.
//  2) rcumsum_kernel: R5 64x1024 shape, __ldcg loads (values now L2-hot).

static constexpr int B = 64;
static constexpr int L = 4096;
static constexpr int D = 256;          // 64 float4 per row
static constexpr int ROWS = B * L;     // 262144
static constexpr int ROWS_PER_BLOCK = 16;   // 8 warps x 2 rows
static constexpr int BLOCKS1 = ROWS / ROWS_PER_BLOCK;  // 16384

__device__ __forceinline__ void st_evict_last(float* p, float v) {
    uint64_t pol;
    asm("createpolicy.fractional.L2::evict_last.b64 %0, 1.0;" : "=l"(pol));
    asm volatile("st.global.L2::cache_hint.f32 [%0], %1, %2;"
                 :: "l"(p), "f"(v), "l"(pol) : "memory");
}

__global__ void __launch_bounds__(256)
dot_kernel(const float4* __restrict__ states4,
           const float4* __restrict__ w4,
           const float*  __restrict__ bias,
           float* __restrict__ out)
{
    const int lane = threadIdx.x & 31;
    const int wid  = threadIdx.x >> 5;

    // warp handles rows r0 = base, r1 = base+1 (one-shot, 4 batched loads)
    const int r0 = blockIdx.x * ROWS_PER_BLOCK + wid * 2;
    const int r1 = r0 + 1;

    const float4* rowp0 = states4 + (size_t)r0 * (D / 4);
    const float4* rowp1 = states4 + (size_t)r1 * (D / 4);

    // 4 back-to-back streaming loads -> 32KB/SM in flight at 64 warps/SM
    float4 a0 = __ldcs(&rowp0[lane]);
    float4 a1 = __ldcs(&rowp0[lane + 32]);
    float4 c0 = __ldcs(&rowp1[lane]);
    float4 c1 = __ldcs(&rowp1[lane + 32]);

    float4 w0 = __ldg(&w4[lane]);
    float4 w1 = __ldg(&w4[lane + 32]);

    float s0 = a0.x * w0.x + a0.y * w0.y + a0.z * w0.z + a0.w * w0.w
             + a1.x * w1.x + a1.y * w1.y + a1.z * w1.z + a1.w * w1.w;
    float s1 = c0.x * w0.x + c0.y * w0.y + c0.z * w0.z + c0.w * w0.w
             + c1.x * w1.x + c1.y * w1.y + c1.z * w1.z + c1.w * w1.w;

    #pragma unroll
    for (int off = 16; off > 0; off >>= 1) {
        s0 += __shfl_xor_sync(0xFFFFFFFFu, s0, off);
        s1 += __shfl_xor_sync(0xFFFFFFFFu, s1, off);
    }

    if (lane == 0) {
        float bv = __ldg(bias);
        st_evict_last(&out[r0], s0 + bv);
        st_evict_last(&out[r1], s1 + bv);
    }
}

// In-place reverse cumulative sum along L for each batch row.
// grid = B blocks x 1024 threads, one float4 per thread. Values L2-hot.
__global__ void __launch_bounds__(1024)
rcumsum_kernel(float* __restrict__ data)
{
    const int b    = blockIdx.x;
    const int t    = threadIdx.x;
    const int lane = t & 31;
    const int wid  = t >> 5;
    float4* p = reinterpret_cast<float4*>(data + (size_t)b * L) + t;

    float4 x = __ldcg(p);                  // L2 hit (~234 cyc) after pinning
    float v0 = x.x, v1 = x.y, v2 = x.z, v3 = x.w;
    float total = v0 + v1 + v2 + v3;

    // inclusive SUFFIX scan within warp: lane i -> sum over lanes >= i
    float s = total;
    #pragma unroll
    for (int off = 1; off < 32; off <<= 1) {
        float n = __shfl_down_sync(0xFFFFFFFFu, s, off);
        if (lane < 32 - off) s += n;
    }

    __shared__ float warp_off[32];
    {
        __shared__ float warp_tot[32];
        if (lane == 0) warp_tot[wid] = s;   // lane 0's s == warp full sum
        __syncthreads();

        if (wid == 0) {
            float ws = warp_tot[lane];
            float ss = ws;
            #pragma unroll
            for (int off = 1; off < 32; off <<= 1) {
                float n = __shfl_down_sync(0xFFFFFFFFu, ss, off);
                if (lane < 32 - off) ss += n;
            }
            warp_off[lane] = ss - ws;       // exclusive suffix of warp sums
        }
        __syncthreads();
    }

    // exclusive suffix for this thread: warps after mine + lanes after me
    float offset = warp_off[wid] + (s - total);

    float q3 = offset + v3;
    float q2 = q3 + v2;
    float q1 = q2 + v1;
    float q0 = q1 + v0;

    *p = make_float4(q0, q1, q2, q3);
}

extern "C" void kernel_launch(void* const* d_in, const int* in_sizes, int n_in,
                              void* d_out, int out_size)
{
    const float4* states4 = (const float4*)d_in[0];
    const float4* w4      = (const float4*)d_in[1];
    const float*  bias    = (const float*)d_in[2];
    float* out = (float*)d_out;

    dot_kernel<<<BLOCKS1, 256>>>(states4, w4, bias, out);
    rcumsum_kernel<<<B, 1024>>>(out);
}

// round 17
// speedup vs baseline: 1.1023x; 1.0066x over previous
#include <cuda_runtime.h>
#include <cstdint>

// Problem: states [B=64, L=4096, D=256] f32; w [256] f32; bias scalar f32.
// out[b,l] = reverse_cumsum_l( dot(states[b,l,:], w) + bias )
//
// Two kernels — recombination of the independently-measured best pieces:
//  1) dot_kernel: EXACT R5 shape (1 row/warp, 2x __ldcs, 32768 x 256thr,
//     measured 38.6us = 6.66 TB/s) + L2::evict_last on the value store so
//     the 1MB of values survives the evict_first stream (R16: kernel2
//     loads become L2 hits).
//  2) rcumsum_kernel: EXACT R16 shape (64 x 1024, __ldcg, measured 4.3us).

static constexpr int B = 64;
static constexpr int L = 4096;
static constexpr int D = 256;          // 64 float4 per row
static constexpr int ROWS = B * L;     // 262144

__device__ __forceinline__ void st_evict_last(float* p, float v) {
    uint64_t pol;
    asm("createpolicy.fractional.L2::evict_last.b64 %0, 1.0;" : "=l"(pol));
    asm volatile("st.global.L2::cache_hint.f32 [%0], %1, %2;"
                 :: "l"(p), "f"(v), "l"(pol) : "memory");
}

__global__ void __launch_bounds__(256)
dot_kernel(const float4* __restrict__ states4,
           const float4* __restrict__ w4,
           const float*  __restrict__ bias,
           float* __restrict__ out)
{
    int gwarp = (blockIdx.x * blockDim.x + threadIdx.x) >> 5;
    int lane  = threadIdx.x & 31;

    const float4* row = states4 + (size_t)gwarp * (D / 4);

    // streaming loads, evict-first: states are touched exactly once
    float4 a0 = __ldcs(&row[lane]);
    float4 a1 = __ldcs(&row[lane + 32]);
    float4 w0 = __ldg(&w4[lane]);
    float4 w1 = __ldg(&w4[lane + 32]);

    float s = a0.x * w0.x + a0.y * w0.y + a0.z * w0.z + a0.w * w0.w
            + a1.x * w1.x + a1.y * w1.y + a1.z * w1.z + a1.w * w1.w;

    #pragma unroll
    for (int off = 16; off > 0; off >>= 1)
        s += __shfl_xor_sync(0xFFFFFFFFu, s, off);

    if (lane == 0)
        st_evict_last(&out[gwarp], s + __ldg(bias));
}

// In-place reverse cumulative sum along L for each batch row.
// grid = B blocks x 1024 threads, one float4 per thread. Values L2-hot.
__global__ void __launch_bounds__(1024)
rcumsum_kernel(float* __restrict__ data)
{
    const int b    = blockIdx.x;
    const int t    = threadIdx.x;
    const int lane = t & 31;
    const int wid  = t >> 5;
    float4* p = reinterpret_cast<float4*>(data + (size_t)b * L) + t;

    float4 x = __ldcg(p);                  // L2 hit after evict_last pinning
    float v0 = x.x, v1 = x.y, v2 = x.z, v3 = x.w;
    float total = v0 + v1 + v2 + v3;

    // inclusive SUFFIX scan within warp: lane i -> sum over lanes >= i
    float s = total;
    #pragma unroll
    for (int off = 1; off < 32; off <<= 1) {
        float n = __shfl_down_sync(0xFFFFFFFFu, s, off);
        if (lane < 32 - off) s += n;
    }

    __shared__ float warp_off[32];
    {
        __shared__ float warp_tot[32];
        if (lane == 0) warp_tot[wid] = s;   // lane 0's s == warp full sum
        __syncthreads();

        if (wid == 0) {
            float ws = warp_tot[lane];
            float ss = ws;
            #pragma unroll
            for (int off = 1; off < 32; off <<= 1) {
                float n = __shfl_down_sync(0xFFFFFFFFu, ss, off);
                if (lane < 32 - off) ss += n;
            }
            warp_off[lane] = ss - ws;       // exclusive suffix of warp sums
        }
        __syncthreads();
    }

    // exclusive suffix for this thread: warps after mine + lanes after me
    float offset = warp_off[wid] + (s - total);

    float q3 = offset + v3;
    float q2 = q3 + v2;
    float q1 = q2 + v1;
    float q0 = q1 + v0;

    *p = make_float4(q0, q1, q2, q3);
}

extern "C" void kernel_launch(void* const* d_in, const int* in_sizes, int n_in,
                              void* d_out, int out_size)
{
    const float4* states4 = (const float4*)d_in[0];
    const float4* w4      = (const float4*)d_in[1];
    const float*  bias    = (const float*)d_in[2];
    float* out = (float*)d_out;

    dot_kernel<<<ROWS / 8, 256>>>(states4, w4, bias, out);
    rcumsum_kernel<<<B, 1024>>>(out);
}